// round 14
// baseline (speedup 1.0000x reference)
#include <cuda_runtime.h>
#include <cstdint>

#define NQ 4
#define NL 6
#define NC 10
#define DIM 512
#define HPI_F 1.57079632679489661923f

#define THREADS 128
#define ROWS 128          // rows per CTA; warp streams 32 rows
#define DEPTH 6           // ring depth in rows (per warp)
#define ROW_BYTES 2048
#define WARP_RING (DEPTH * ROW_BYTES)     // 12288

// dynamic smem layout
#define OFF_RING   0                       // 4 warps * 12288 = 49152 (reused as souts)
#define OFF_SPART  49152                   // 128 rows * 2 * 16B = 4096
#define OFF_SU     (OFF_SPART + 4096)      // 2048
#define OFF_SG     (OFF_SU + 2048)         // 768
#define SMEM_TOTAL (OFF_SG + 768 + 64)     // 56128

typedef unsigned long long ull;

__device__ __forceinline__ void fma2(ull& d, ull a, ull b, ull c) {
    asm("fma.rn.f32x2 %0, %1, %2, %3;" : "=l"(d) : "l"(a), "l"(b), "l"(c));
}
__device__ __forceinline__ ull pack2(float lo, float hi) {
    ull r;
    asm("mov.b64 %0, {%1, %2};" : "=l"(r) : "r"(__float_as_uint(lo)), "r"(__float_as_uint(hi)));
    return r;
}
__device__ __forceinline__ void unpack2(ull v, float& lo, float& hi) {
    unsigned int a, b;
    asm("mov.b64 {%0, %1}, %2;" : "=r"(a), "=r"(b) : "l"(v));
    lo = __uint_as_float(a); hi = __uint_as_float(b);
}
__device__ __forceinline__ uint32_t smem_u32(const void* p) {
    uint32_t a;
    asm("{ .reg .u64 t; cvta.to.shared.u64 t, %1; cvt.u32.u64 %0, t; }" : "=r"(a) : "l"(p));
    return a;
}
__device__ __forceinline__ void cp_async16(uint32_t dst, const void* src) {
    asm volatile("cp.async.cg.shared.global [%0], [%1], 16;" :: "r"(dst), "l"(src) : "memory");
}
__device__ __forceinline__ void cp_commit() {
    asm volatile("cp.async.commit_group;" ::: "memory");
}
template <int N>
__device__ __forceinline__ void cp_wait() {
    asm volatile("cp.async.wait_group %0;" :: "n"(N) : "memory");
}

// Build the 16x16 circuit matrix U into sU. Each warp evolves 4 basis
// columns: two independent chains interleaved so shfl latencies overlap.
__device__ __forceinline__ void build_U(float2* sU, const float (*sg)[8],
                                        int warp, int lane) {
    const int i = lane & 15;
    const int sub = lane >> 4;
    const int j0 = warp * 4 + sub;
    const int j1 = warp * 4 + 2 + sub;

    float reA = (i == j0) ? 1.0f : 0.0f, imA = 0.0f;
    float reB = (i == j1) ? 1.0f : 0.0f, imB = 0.0f;

#pragma unroll
    for (int l = 0; l < NL; l++) {
#pragma unroll
        for (int w = 0; w < NQ; w++) {
            const float* g = sg[l * NQ + w];
            int m = 8 >> w;
            float pA = __shfl_xor_sync(0xffffffffu, reA, m);
            float qA = __shfl_xor_sync(0xffffffffu, imA, m);
            float pB = __shfl_xor_sync(0xffffffffu, reB, m);
            float qB = __shfl_xor_sync(0xffffffffu, imB, m);
            bool low = (i & m) == 0;
            float orr = low ? g[0] : g[6];
            float oii = low ? g[1] : g[7];
            float crr = low ? g[2] : g[4];
            float cii = low ? g[3] : g[5];
            float nreA = orr * reA - oii * imA + crr * pA - cii * qA;
            float nimA = orr * imA + oii * reA + crr * qA + cii * pA;
            float nreB = orr * reB - oii * imB + crr * pB - cii * qB;
            float nimB = orr * imB + oii * reB + crr * qB + cii * pB;
            reA = nreA; imA = nimA; reB = nreB; imB = nimB;
        }
        int r = l % (NQ - 1) + 1;
#pragma unroll
        for (int w = 0; w < NQ; w++) {
            int cmask = 8 >> w;
            int tmask = 8 >> ((w + r) & 3);
            int src_i = (i & cmask) ? (i ^ tmask) : i;
            int srcLane = (lane & 16) | src_i;
            reA = __shfl_sync(0xffffffffu, reA, srcLane);
            imA = __shfl_sync(0xffffffffu, imA, srcLane);
            reB = __shfl_sync(0xffffffffu, reB, srcLane);
            imB = __shfl_sync(0xffffffffu, imB, srcLane);
        }
    }
    sU[j0 * 16 + i] = make_float2(reA, imA);
    sU[j1 * 16 + i] = make_float2(reB, imB);
}

// consume one ring slot into acc (8 f32x2 FMAs x 4 outputs)
__device__ __forceinline__ void row_fma(const char* ringc, int slot, int lane,
                                        const ull wq[4][8], ull acc[4]) {
    const ulonglong2* sp2 = (const ulonglong2*)(ringc + slot * ROW_BYTES);
    ull xv[8];
#pragma unroll
    for (int jj = 0; jj < 4; jj++) {
        ulonglong2 t = sp2[jj * 32 + lane];
        xv[2 * jj] = t.x; xv[2 * jj + 1] = t.y;
    }
#pragma unroll
    for (int jj = 0; jj < 8; jj++)
#pragma unroll
        for (int w = 0; w < 4; w++)
            fma2(acc[w], xv[jj], wq[w][jj], acc[w]);
}

// interleaved 4-level reduction + partial store (lanes 0,1) for a row pair
__device__ __forceinline__ void pair_reduce_store(
    ull accA[4], ull accB[4], float4* spart, int rowA, int rowB, int lane) {
    float aA[4], aB[4];
#pragma unroll
    for (int w = 0; w < 4; w++) {
        float lo, hi;
        unpack2(accA[w], lo, hi); aA[w] = lo + hi;
        unpack2(accB[w], lo, hi); aB[w] = lo + hi;
    }
#pragma unroll
    for (int off = 16; off >= 2; off >>= 1) {
#pragma unroll
        for (int w = 0; w < 4; w++) {
            aA[w] += __shfl_xor_sync(0xffffffffu, aA[w], off);
            aB[w] += __shfl_xor_sync(0xffffffffu, aB[w], off);
        }
    }
    if (lane < 2) {
        spart[rowA * 2 + lane] = make_float4(aA[0], aA[1], aA[2], aA[3]);
        spart[rowB * 2 + lane] = make_float4(aB[0], aB[1], aB[2], aB[3]);
    }
}

// ---------------------------------------------------------------------------
// Fused kernel: staggered phases + depth-6 per-warp cp.async ring (3-iteration
// issue->wait distance clears DRAM latency) + paired rows, hoisted refills.
// ---------------------------------------------------------------------------
__global__ __launch_bounds__(THREADS, 4) void vqc_fused_kernel(
    const float* __restrict__ x,
    const float* __restrict__ Wpre,
    const float* __restrict__ bpre,
    const float* __restrict__ qw,
    const float* __restrict__ Wpost,
    const float* __restrict__ bpost,
    float* __restrict__ out)
{
    extern __shared__ char dynsmem[];
    float4* spart = (float4*)(dynsmem + OFF_SPART);
    float2* sU    = (float2*)(dynsmem + OFF_SU);
    float (*sg)[8] = (float(*)[8])(dynsmem + OFF_SG);

    const int tid  = threadIdx.x;
    const int lane = tid & 31;
    const int warp = tid >> 5;
    const int row0 = blockIdx.x * ROWS;
    const int wrow0 = row0 + warp * 32;
    const bool uFirst = (blockIdx.x & 1) == 0;

    char* ringc = dynsmem + OFF_RING + warp * WARP_RING;
    const uint32_t ring_u32 = smem_u32(ringc) + lane * 16;
    const char* xg = (const char*)x + (size_t)wrow0 * ROW_BYTES + lane * 16;

    // ---- prologue: fill the ring (rows 0..5), one commit group per row ----
#pragma unroll
    for (int r = 0; r < DEPTH; r++) {
#pragma unroll
        for (int j = 0; j < 4; j++)
            cp_async16(ring_u32 + r * ROW_BYTES + j * 512,
                       xg + (size_t)r * ROW_BYTES + j * 512);
        cp_commit();
    }

    // ---- W_pre into registers as f32x2 pairs ----
    const ulonglong2* W2 = (const ulonglong2*)Wpre;   // [4][128] 16B units
    ull wq[4][8];
#pragma unroll
    for (int w = 0; w < 4; w++)
#pragma unroll
        for (int jj = 0; jj < 4; jj++) {
            ulonglong2 t = W2[w * 128 + jj * 32 + lane];
            wq[w][2 * jj] = t.x; wq[w][2 * jj + 1] = t.y;
        }

    // gate coefficients (fast sincos: |args| << 1, abs err ~1e-7)
    if (tid < 24) {
        float phi = qw[tid * 3 + 0];
        float th  = qw[tid * 3 + 1];
        float om  = qw[tid * 3 + 2];
        float st, ct; __sincosf(0.5f * th, &st, &ct);
        float sa, ca; __sincosf(0.5f * (phi + om), &sa, &ca);
        float sb, cb; __sincosf(0.5f * (phi - om), &sb, &cb);
        sg[tid][0] =  ca * ct;  sg[tid][1] = -sa * ct;   // g00
        sg[tid][2] = -cb * st;  sg[tid][3] = -sb * st;   // g01
        sg[tid][4] =  cb * st;  sg[tid][5] = -sb * st;   // g10
        sg[tid][6] =  ca * ct;  sg[tid][7] =  sa * ct;   // g11
    }
    __syncthreads();

    // ---- Phase 0 (even CTAs): build U before streaming ----
    if (uFirst) build_U(sU, sg, warp, lane);

    // ---- Phase 1: ring-streamed GEMV, two rows per iteration ----
    const int sbase = warp * 32;
#pragma unroll 2
    for (int p = 0; p < 13; p++) {
        const int r0 = 2 * p, r1 = 2 * p + 1;
        const int s0 = r0 % 6, s1 = r1 % 6;
        cp_wait<4>();                       // rows r0, r1 landed

        ull accA[4] = {0ull, 0ull, 0ull, 0ull};
        ull accB[4] = {0ull, 0ull, 0ull, 0ull};
        row_fma(ringc, s0, lane, wq, accA);
        row_fma(ringc, s1, lane, wq, accB);

        // refill both slots BEFORE the reduction chain (independent of it)
#pragma unroll
        for (int j = 0; j < 4; j++)
            cp_async16(ring_u32 + s0 * ROW_BYTES + j * 512,
                       xg + (size_t)(r0 + DEPTH) * ROW_BYTES + j * 512);
        cp_commit();
#pragma unroll
        for (int j = 0; j < 4; j++)
            cp_async16(ring_u32 + s1 * ROW_BYTES + j * 512,
                       xg + (size_t)(r1 + DEPTH) * ROW_BYTES + j * 512);
        cp_commit();

        pair_reduce_store(accA, accB, spart, sbase + r0, sbase + r1, lane);
    }
    // epilogue pairs: rows 26..31 (outstanding groups drain without refills)
    {
        cp_wait<4>();     // rows 26,27
        ull accA[4] = {0ull, 0ull, 0ull, 0ull};
        ull accB[4] = {0ull, 0ull, 0ull, 0ull};
        row_fma(ringc, 26 % 6, lane, wq, accA);
        row_fma(ringc, 27 % 6, lane, wq, accB);
        pair_reduce_store(accA, accB, spart, sbase + 26, sbase + 27, lane);
    }
    {
        cp_wait<2>();     // rows 28,29
        ull accA[4] = {0ull, 0ull, 0ull, 0ull};
        ull accB[4] = {0ull, 0ull, 0ull, 0ull};
        row_fma(ringc, 28 % 6, lane, wq, accA);
        row_fma(ringc, 29 % 6, lane, wq, accB);
        pair_reduce_store(accA, accB, spart, sbase + 28, sbase + 29, lane);
    }
    {
        cp_wait<0>();     // rows 30,31
        ull accA[4] = {0ull, 0ull, 0ull, 0ull};
        ull accB[4] = {0ull, 0ull, 0ull, 0ull};
        row_fma(ringc, 30 % 6, lane, wq, accA);
        row_fma(ringc, 31 % 6, lane, wq, accB);
        pair_reduce_store(accA, accB, spart, sbase + 30, sbase + 31, lane);
    }

    // ---- Phase 0 (odd CTAs): build U after streaming ----
    if (!uFirst) build_U(sU, sg, warp, lane);
    __syncthreads();

    // ---- Phase 2: thread-per-row quantum ----
    float4 pa = spart[tid * 2 + 0];
    float4 pb4 = spart[tid * 2 + 1];
    float pv[4] = {pa.x + pb4.x + bpre[0], pa.y + pb4.y + bpre[1],
                   pa.z + pb4.z + bpre[2], pa.w + pb4.w + bpre[3]};

    float cw[4], sw[4];
#pragma unroll
    for (int w = 0; w < 4; w++) {
        float e = __expf(2.0f * pv[w]);
        float t = 1.0f - __fdividef(2.0f, e + 1.0f);   // tanh
        float h = HPI_F * t;
        sw[w] = __sinf(h);
        cw[w] = __cosf(h);
    }

    float p01[4], p23[4], v[16];
    p01[0] = cw[0] * cw[1]; p01[1] = cw[0] * sw[1];
    p01[2] = sw[0] * cw[1]; p01[3] = sw[0] * sw[1];
    p23[0] = cw[2] * cw[3]; p23[1] = cw[2] * sw[3];
    p23[2] = sw[2] * cw[3]; p23[3] = sw[2] * sw[3];
#pragma unroll
    for (int a = 0; a < 4; a++)
#pragma unroll
        for (int b = 0; b < 4; b++)
            v[a * 4 + b] = p01[a] * p23[b];

    ull acc64[16];
#pragma unroll
    for (int i = 0; i < 16; i++) acc64[i] = 0ull;
    const ull* sU64 = (const ull*)sU;
#pragma unroll
    for (int jcol = 0; jcol < 16; jcol++) {
        ull vj2 = pack2(v[jcol], v[jcol]);
#pragma unroll
        for (int i = 0; i < 16; i++)
            fma2(acc64[i], sU64[jcol * 16 + i], vj2, acc64[i]);
    }

    float pb[16];
#pragma unroll
    for (int i = 0; i < 16; i++) {
        float re, im; unpack2(acc64[i], re, im);
        pb[i] = re * re + im * im;
    }

    float q[4];
#pragma unroll
    for (int w = 0; w < 4; w++) {
        int m = 8 >> w;
        float s = 0.0f;
#pragma unroll
        for (int i = 0; i < 16; i++) s += (i & m) ? -pb[i] : pb[i];
        q[w] = s;
    }

    float res[NC];
#pragma unroll
    for (int c = 0; c < NC; c++) {
        float o = bpost[c];
#pragma unroll
        for (int w = 0; w < 4; w++) o = fmaf(q[w], Wpost[c * 4 + w], o);
        res[c] = o;
    }

    // stage outputs in the (now dead) ring region for coalesced stores
    __syncthreads();
    float* souts = (float*)(dynsmem + OFF_RING);
#pragma unroll
    for (int c = 0; c < NC; c++) souts[tid * NC + c] = res[c];
    __syncthreads();

    size_t obase = (size_t)row0 * NC;
    for (int i = tid; i < ROWS * NC; i += THREADS)
        out[obase + i] = souts[i];
}

// ---------------------------------------------------------------------------
extern "C" void kernel_launch(void* const* d_in, const int* in_sizes, int n_in,
                              void* d_out, int out_size) {
    const float* x     = (const float*)d_in[0];
    const float* Wpre  = (const float*)d_in[1];
    const float* bpre  = (const float*)d_in[2];
    const float* qw    = (const float*)d_in[3];
    const float* Wpost = (const float*)d_in[4];
    const float* bpost = (const float*)d_in[5];
    float* out = (float*)d_out;

    static bool attr_set = false;
    if (!attr_set) {
        cudaFuncSetAttribute(vqc_fused_kernel,
                             cudaFuncAttributeMaxDynamicSharedMemorySize, SMEM_TOTAL);
        attr_set = true;
    }

    int B = in_sizes[0] / DIM;   // 65536
    vqc_fused_kernel<<<B / ROWS, THREADS, SMEM_TOTAL>>>(
        x, Wpre, bpre, qw, Wpost, bpost, out);
}

// round 15
// speedup vs baseline: 1.0707x; 1.0707x over previous
#include <cuda_runtime.h>
#include <cstdint>

#define NQ 4
#define NL 6
#define NC 10
#define DIM 512
#define HPI_F 1.57079632679489661923f

#define THREADS 128
#define ROWS 128          // rows per CTA; warp streams 32 rows
#define DEPTH 4           // ring depth in rows (per warp)
#define ROW_BYTES 2048
#define WARP_RING (DEPTH * ROW_BYTES)     // 8192

// dynamic smem layout
#define OFF_RING   0                       // 4 warps * 8192 = 32768
#define OFF_SPART  32768                   // 128 rows * 8 * 16B = 16384
#define OFF_SU     (OFF_SPART + 16384)     // 2048
#define OFF_SG     (OFF_SU + 2048)         // 768
#define SMEM_TOTAL (OFF_SG + 768)          // 51968

typedef unsigned long long ull;

__device__ __forceinline__ void fma2(ull& d, ull a, ull b, ull c) {
    asm("fma.rn.f32x2 %0, %1, %2, %3;" : "=l"(d) : "l"(a), "l"(b), "l"(c));
}
__device__ __forceinline__ ull pack2(float lo, float hi) {
    ull r;
    asm("mov.b64 %0, {%1, %2};" : "=l"(r) : "r"(__float_as_uint(lo)), "r"(__float_as_uint(hi)));
    return r;
}
__device__ __forceinline__ void unpack2(ull v, float& lo, float& hi) {
    unsigned int a, b;
    asm("mov.b64 {%0, %1}, %2;" : "=r"(a), "=r"(b) : "l"(v));
    lo = __uint_as_float(a); hi = __uint_as_float(b);
}
__device__ __forceinline__ uint32_t smem_u32(const void* p) {
    uint32_t a;
    asm("{ .reg .u64 t; cvta.to.shared.u64 t, %1; cvt.u32.u64 %0, t; }" : "=r"(a) : "l"(p));
    return a;
}
__device__ __forceinline__ void cp_async16(uint32_t dst, const void* src) {
    asm volatile("cp.async.cg.shared.global [%0], [%1], 16;" :: "r"(dst), "l"(src) : "memory");
}
__device__ __forceinline__ void cp_commit() {
    asm volatile("cp.async.commit_group;" ::: "memory");
}
template <int N>
__device__ __forceinline__ void cp_wait() {
    asm volatile("cp.async.wait_group %0;" :: "n"(N) : "memory");
}

// Build the 16x16 circuit matrix U into sU. Each warp evolves 4 basis
// columns: two independent chains interleaved so shfl latencies overlap.
__device__ __forceinline__ void build_U(float2* sU, const float (*sg)[8],
                                        int warp, int lane) {
    const int i = lane & 15;
    const int sub = lane >> 4;
    const int j0 = warp * 4 + sub;
    const int j1 = warp * 4 + 2 + sub;

    float reA = (i == j0) ? 1.0f : 0.0f, imA = 0.0f;
    float reB = (i == j1) ? 1.0f : 0.0f, imB = 0.0f;

#pragma unroll
    for (int l = 0; l < NL; l++) {
#pragma unroll
        for (int w = 0; w < NQ; w++) {
            const float* g = sg[l * NQ + w];
            int m = 8 >> w;
            float pA = __shfl_xor_sync(0xffffffffu, reA, m);
            float qA = __shfl_xor_sync(0xffffffffu, imA, m);
            float pB = __shfl_xor_sync(0xffffffffu, reB, m);
            float qB = __shfl_xor_sync(0xffffffffu, imB, m);
            bool low = (i & m) == 0;
            float orr = low ? g[0] : g[6];
            float oii = low ? g[1] : g[7];
            float crr = low ? g[2] : g[4];
            float cii = low ? g[3] : g[5];
            float nreA = orr * reA - oii * imA + crr * pA - cii * qA;
            float nimA = orr * imA + oii * reA + crr * qA + cii * pA;
            float nreB = orr * reB - oii * imB + crr * pB - cii * qB;
            float nimB = orr * imB + oii * reB + crr * qB + cii * pB;
            reA = nreA; imA = nimA; reB = nreB; imB = nimB;
        }
        int r = l % (NQ - 1) + 1;
#pragma unroll
        for (int w = 0; w < NQ; w++) {
            int cmask = 8 >> w;
            int tmask = 8 >> ((w + r) & 3);
            int src_i = (i & cmask) ? (i ^ tmask) : i;
            int srcLane = (lane & 16) | src_i;
            reA = __shfl_sync(0xffffffffu, reA, srcLane);
            imA = __shfl_sync(0xffffffffu, imA, srcLane);
            reB = __shfl_sync(0xffffffffu, reB, srcLane);
            imB = __shfl_sync(0xffffffffu, imB, srcLane);
        }
    }
    sU[j0 * 16 + i] = make_float2(reA, imA);
    sU[j1 * 16 + i] = make_float2(reB, imB);
}

// consume one ring slot into acc (8 f32x2 FMAs x 4 outputs)
__device__ __forceinline__ void row_fma(const char* ringc, int slot, int lane,
                                        const ull wq[4][8], ull acc[4]) {
    const ulonglong2* sp2 = (const ulonglong2*)(ringc + slot * ROW_BYTES);
    ull xv[8];
#pragma unroll
    for (int jj = 0; jj < 4; jj++) {
        ulonglong2 t = sp2[jj * 32 + lane];
        xv[2 * jj] = t.x; xv[2 * jj + 1] = t.y;
    }
#pragma unroll
    for (int jj = 0; jj < 8; jj++)
#pragma unroll
        for (int w = 0; w < 4; w++)
            fma2(acc[w], xv[jj], wq[w][jj], acc[w]);
}

// interleaved 2-level reduction + partial store for a pair of rows
__device__ __forceinline__ void pair_reduce_store(
    ull accA[4], ull accB[4], float4* spart, int rowA, int rowB, int lane) {
    float aA[4], aB[4];
#pragma unroll
    for (int w = 0; w < 4; w++) {
        float lo, hi;
        unpack2(accA[w], lo, hi); aA[w] = lo + hi;
        unpack2(accB[w], lo, hi); aB[w] = lo + hi;
    }
#pragma unroll
    for (int w = 0; w < 4; w++) {
        aA[w] += __shfl_xor_sync(0xffffffffu, aA[w], 16);
        aB[w] += __shfl_xor_sync(0xffffffffu, aB[w], 16);
    }
#pragma unroll
    for (int w = 0; w < 4; w++) {
        aA[w] += __shfl_xor_sync(0xffffffffu, aA[w], 8);
        aB[w] += __shfl_xor_sync(0xffffffffu, aB[w], 8);
    }
    if (lane < 8) {
        spart[rowA * 8 + lane] = make_float4(aA[0], aA[1], aA[2], aA[3]);
        spart[rowB * 8 + lane] = make_float4(aB[0], aB[1], aB[2], aB[3]);
    }
}

// ---------------------------------------------------------------------------
// Fused kernel: R13 structure with single commit group per row-pair and
// direct global stores for the output (no smem staging in the tail).
// ---------------------------------------------------------------------------
__global__ __launch_bounds__(THREADS, 4) void vqc_fused_kernel(
    const float* __restrict__ x,
    const float* __restrict__ Wpre,
    const float* __restrict__ bpre,
    const float* __restrict__ qw,
    const float* __restrict__ Wpost,
    const float* __restrict__ bpost,
    float* __restrict__ out)
{
    extern __shared__ char dynsmem[];
    float4* spart = (float4*)(dynsmem + OFF_SPART);
    float2* sU    = (float2*)(dynsmem + OFF_SU);
    float (*sg)[8] = (float(*)[8])(dynsmem + OFF_SG);

    const int tid  = threadIdx.x;
    const int lane = tid & 31;
    const int warp = tid >> 5;
    const int row0 = blockIdx.x * ROWS;
    const int wrow0 = row0 + warp * 32;
    const bool uFirst = (blockIdx.x & 1) == 0;

    char* ringc = dynsmem + OFF_RING + warp * WARP_RING;
    const uint32_t ring_u32 = smem_u32(ringc) + lane * 16;
    const char* xg = (const char*)x + (size_t)wrow0 * ROW_BYTES + lane * 16;

    // ---- prologue: fill ring rows 0..3, ONE commit group per row-pair ----
#pragma unroll
    for (int pr = 0; pr < 2; pr++) {
#pragma unroll
        for (int r = 2 * pr; r < 2 * pr + 2; r++)
#pragma unroll
            for (int j = 0; j < 4; j++)
                cp_async16(ring_u32 + r * ROW_BYTES + j * 512,
                           xg + (size_t)r * ROW_BYTES + j * 512);
        cp_commit();
    }

    // ---- W_pre into registers as f32x2 pairs ----
    const ulonglong2* W2 = (const ulonglong2*)Wpre;   // [4][128] 16B units
    ull wq[4][8];
#pragma unroll
    for (int w = 0; w < 4; w++)
#pragma unroll
        for (int jj = 0; jj < 4; jj++) {
            ulonglong2 t = W2[w * 128 + jj * 32 + lane];
            wq[w][2 * jj] = t.x; wq[w][2 * jj + 1] = t.y;
        }

    // gate coefficients (fast sincos: |args| << 1, abs err ~1e-7)
    if (tid < 24) {
        float phi = qw[tid * 3 + 0];
        float th  = qw[tid * 3 + 1];
        float om  = qw[tid * 3 + 2];
        float st, ct; __sincosf(0.5f * th, &st, &ct);
        float sa, ca; __sincosf(0.5f * (phi + om), &sa, &ca);
        float sb, cb; __sincosf(0.5f * (phi - om), &sb, &cb);
        sg[tid][0] =  ca * ct;  sg[tid][1] = -sa * ct;   // g00
        sg[tid][2] = -cb * st;  sg[tid][3] = -sb * st;   // g01
        sg[tid][4] =  cb * st;  sg[tid][5] = -sb * st;   // g10
        sg[tid][6] =  ca * ct;  sg[tid][7] =  sa * ct;   // g11
    }
    __syncthreads();

    // ---- Phase 0 (even CTAs): build U before streaming ----
    if (uFirst) build_U(sU, sg, warp, lane);

    // ---- Phase 1: ring-streamed GEMV, two rows per iteration ----
    const int sbase = warp * 32;
#pragma unroll 2
    for (int p = 0; p < 14; p++) {
        const int r0 = 2 * p, r1 = 2 * p + 1;
        cp_wait<1>();                       // pair group for r0,r1 landed

        ull accA[4] = {0ull, 0ull, 0ull, 0ull};
        ull accB[4] = {0ull, 0ull, 0ull, 0ull};
        row_fma(ringc, r0 & 3, lane, wq, accA);
        row_fma(ringc, r1 & 3, lane, wq, accB);

        // refill both slots BEFORE the reduction chain (independent of it)
#pragma unroll
        for (int j = 0; j < 4; j++)
            cp_async16(ring_u32 + (r0 & 3) * ROW_BYTES + j * 512,
                       xg + (size_t)(r0 + 4) * ROW_BYTES + j * 512);
#pragma unroll
        for (int j = 0; j < 4; j++)
            cp_async16(ring_u32 + (r1 & 3) * ROW_BYTES + j * 512,
                       xg + (size_t)(r1 + 4) * ROW_BYTES + j * 512);
        cp_commit();

        pair_reduce_store(accA, accB, spart, sbase + r0, sbase + r1, lane);
    }
    // epilogue pairs: rows 28..31 (groups drain without refills)
    {
        cp_wait<1>();     // rows 28,29 (group issued at p=12)
        ull accA[4] = {0ull, 0ull, 0ull, 0ull};
        ull accB[4] = {0ull, 0ull, 0ull, 0ull};
        row_fma(ringc, 28 & 3, lane, wq, accA);
        row_fma(ringc, 29 & 3, lane, wq, accB);
        pair_reduce_store(accA, accB, spart, sbase + 28, sbase + 29, lane);
    }
    {
        cp_wait<0>();     // rows 30,31
        ull accA[4] = {0ull, 0ull, 0ull, 0ull};
        ull accB[4] = {0ull, 0ull, 0ull, 0ull};
        row_fma(ringc, 30 & 3, lane, wq, accA);
        row_fma(ringc, 31 & 3, lane, wq, accB);
        pair_reduce_store(accA, accB, spart, sbase + 30, sbase + 31, lane);
    }

    // ---- Phase 0 (odd CTAs): build U after streaming ----
    if (!uFirst) build_U(sU, sg, warp, lane);
    __syncthreads();

    // ---- Phase 2: thread-per-row quantum ----
    float4 pre4 = make_float4(bpre[0], bpre[1], bpre[2], bpre[3]);
#pragma unroll
    for (int k = 0; k < 8; k++) {
        float4 p = spart[tid * 8 + ((tid + k) & 7)];   // bank-swizzled
        pre4.x += p.x; pre4.y += p.y; pre4.z += p.z; pre4.w += p.w;
    }

    float cw[4], sw[4];
    {
        float pv[4] = {pre4.x, pre4.y, pre4.z, pre4.w};
#pragma unroll
        for (int w = 0; w < 4; w++) {
            float e = __expf(2.0f * pv[w]);
            float t = 1.0f - __fdividef(2.0f, e + 1.0f);   // tanh
            float h = HPI_F * t;
            sw[w] = __sinf(h);
            cw[w] = __cosf(h);
        }
    }

    float p01[4], p23[4], v[16];
    p01[0] = cw[0] * cw[1]; p01[1] = cw[0] * sw[1];
    p01[2] = sw[0] * cw[1]; p01[3] = sw[0] * sw[1];
    p23[0] = cw[2] * cw[3]; p23[1] = cw[2] * sw[3];
    p23[2] = sw[2] * cw[3]; p23[3] = sw[2] * sw[3];
#pragma unroll
    for (int a = 0; a < 4; a++)
#pragma unroll
        for (int b = 0; b < 4; b++)
            v[a * 4 + b] = p01[a] * p23[b];

    ull acc64[16];
#pragma unroll
    for (int i = 0; i < 16; i++) acc64[i] = 0ull;
    const ull* sU64 = (const ull*)sU;
#pragma unroll
    for (int jcol = 0; jcol < 16; jcol++) {
        ull vj2 = pack2(v[jcol], v[jcol]);
#pragma unroll
        for (int i = 0; i < 16; i++)
            fma2(acc64[i], sU64[jcol * 16 + i], vj2, acc64[i]);
    }

    float pb[16];
#pragma unroll
    for (int i = 0; i < 16; i++) {
        float re, im; unpack2(acc64[i], re, im);
        pb[i] = re * re + im * im;
    }

    float q[4];
#pragma unroll
    for (int w = 0; w < 4; w++) {
        int m = 8 >> w;
        float s = 0.0f;
#pragma unroll
        for (int i = 0; i < 16; i++) s += (i & m) ? -pb[i] : pb[i];
        q[w] = s;
    }

    // post linear, written directly: 5x STG.64 per thread (row*40B is 8-aligned)
    float res[NC];
#pragma unroll
    for (int c = 0; c < NC; c++) {
        float o = bpost[c];
#pragma unroll
        for (int w = 0; w < 4; w++) o = fmaf(q[w], Wpost[c * 4 + w], o);
        res[c] = o;
    }
    float2* op = (float2*)(out + (size_t)(row0 + tid) * NC);
#pragma unroll
    for (int c = 0; c < 5; c++)
        op[c] = make_float2(res[2 * c], res[2 * c + 1]);
}

// ---------------------------------------------------------------------------
extern "C" void kernel_launch(void* const* d_in, const int* in_sizes, int n_in,
                              void* d_out, int out_size) {
    const float* x     = (const float*)d_in[0];
    const float* Wpre  = (const float*)d_in[1];
    const float* bpre  = (const float*)d_in[2];
    const float* qw    = (const float*)d_in[3];
    const float* Wpost = (const float*)d_in[4];
    const float* bpost = (const float*)d_in[5];
    float* out = (float*)d_out;

    static bool attr_set = false;
    if (!attr_set) {
        cudaFuncSetAttribute(vqc_fused_kernel,
                             cudaFuncAttributeMaxDynamicSharedMemorySize, SMEM_TOTAL);
        attr_set = true;
    }

    int B = in_sizes[0] / DIM;   // 65536
    vqc_fused_kernel<<<B / ROWS, THREADS, SMEM_TOTAL>>>(
        x, Wpre, bpre, qw, Wpost, bpost, out);
}